// round 9
// baseline (speedup 1.0000x reference)
#include <cuda_runtime.h>
#include <cuda_bf16.h>
#include <cstdint>

// Problem: H[8,4096,1024] G[8,1024,768] Wq[256,768] Wk[256,1024] -> Z[8,1024,1024]
#define B_  8
#define L_  4096
#define DH_ 1024
#define T_  1024
#define DG_ 768
#define P_  256

// ---------------------------------------------------------------------------
// PTX helpers — base-target (sm_80+) features only: mma.sync, ldmatrix, cp.async
// ---------------------------------------------------------------------------
__device__ __forceinline__ uint32_t smem_to_u32(const void* p) {
    uint32_t a;
    asm("{ .reg .u64 t; cvta.to.shared.u64 t, %1; cvt.u32.u64 %0, t; }" : "=r"(a) : "l"(p));
    return a;
}
#define CP_ASYNC16(sa, g) \
    asm volatile("cp.async.cg.shared.global [%0], [%1], 16;" :: "r"(sa), "l"(g))
#define CP_COMMIT() asm volatile("cp.async.commit_group;")
#define CP_WAIT2()  asm volatile("cp.async.wait_group 2;")

#define LDSM_X4(r0, r1, r2, r3, addr) \
    asm volatile("ldmatrix.sync.aligned.m8n8.x4.shared.b16 {%0,%1,%2,%3}, [%4];" \
                 : "=r"(r0), "=r"(r1), "=r"(r2), "=r"(r3) : "r"(addr))
#define LDSM_X4_T(r0, r1, r2, r3, addr) \
    asm volatile("ldmatrix.sync.aligned.m8n8.x4.trans.shared.b16 {%0,%1,%2,%3}, [%4];" \
                 : "=r"(r0), "=r"(r1), "=r"(r2), "=r"(r3) : "r"(addr))

__device__ __forceinline__ void mma16816(float* d, const uint32_t* a, const uint32_t* b) {
    asm volatile(
        "mma.sync.aligned.m16n8k16.row.col.f32.bf16.bf16.f32 "
        "{%0,%1,%2,%3}, {%4,%5,%6,%7}, {%8,%9}, {%0,%1,%2,%3};"
        : "+f"(d[0]), "+f"(d[1]), "+f"(d[2]), "+f"(d[3])
        : "r"(a[0]), "r"(a[1]), "r"(a[2]), "r"(a[3]), "r"(b[0]), "r"(b[1]));
}

__device__ __forceinline__ void split1(float f, __nv_bfloat16& h, __nv_bfloat16& l) {
    h = __float2bfloat16(f);
    l = __float2bfloat16(f - __bfloat162float(h));
}
__device__ __forceinline__ uint32_t pack2(__nv_bfloat16 a, __nv_bfloat16 b) {
    return ((uint32_t)*(uint16_t*)&b << 16) | *(uint16_t*)&a;
}

// ---------------------------------------------------------------------------
// Scratch (device globals; allocation-free)
// ---------------------------------------------------------------------------
__device__ __align__(16) __nv_bfloat16 g_Ghi[(size_t)B_*T_*DG_],  g_Glo[(size_t)B_*T_*DG_];
__device__ __align__(16) __nv_bfloat16 g_Wqhi[(size_t)P_*DG_],    g_Wqlo[(size_t)P_*DG_];
__device__ __align__(16) __nv_bfloat16 g_Wkhi[(size_t)P_*DH_],    g_Wklo[(size_t)P_*DH_];
__device__ __align__(16) __nv_bfloat16 g_Hhi[(size_t)B_*L_*DH_],  g_Hlo[(size_t)B_*L_*DH_];
__device__ __align__(16) __nv_bfloat16 g_Qhi[(size_t)B_*T_*P_],   g_Qlo[(size_t)B_*T_*P_];
__device__ __align__(16) __nv_bfloat16 g_Khi[(size_t)B_*L_*P_],   g_Klo[(size_t)B_*L_*P_];
__device__ __align__(16) __nv_bfloat16 g_Phi[(size_t)B_*T_*L_],   g_Plo[(size_t)B_*T_*L_];
__device__ float g_sum[(size_t)B_*T_];

// ---------------------------------------------------------------------------
// Elementwise fp32 -> bf16 hi/lo split
// ---------------------------------------------------------------------------
__global__ __launch_bounds__(256) void split_f32(
    const float* __restrict__ x, __nv_bfloat16* __restrict__ hi,
    __nv_bfloat16* __restrict__ lo, int n4)
{
    int i = blockIdx.x * 256 + threadIdx.x;
    if (i >= n4) return;
    float4 v = ((const float4*)x)[i];
    __nv_bfloat16 h0,h1,h2,h3,l0,l1,l2,l3;
    split1(v.x,h0,l0); split1(v.y,h1,l1); split1(v.z,h2,l2); split1(v.w,h3,l3);
    ((uint2*)hi)[i] = make_uint2(pack2(h0,h1), pack2(h2,h3));
    ((uint2*)lo)[i] = make_uint2(pack2(l0,l1), pack2(l2,l3));
}

__global__ __launch_bounds__(256) void zero_f32(float* __restrict__ p, int n) {
    int i = blockIdx.x * 256 + threadIdx.x;
    if (i < n) p[i] = 0.f;
}

// ---------------------------------------------------------------------------
// HMMA bf16 3-split NT GEMM:  C[M,N] = (Ahi+Alo)[M,K] * (Bhi+Blo)[N,K]^T
// BM=128, BN=256, BK=32, 512 threads = 16 warps (2M x 8N), 3-stage cp.async.
// Register-lean inner loop: (ah,bh),(ah,bl) then ah<-al,(al,bh).
// EPI 1: write Chi/Clo bf16 split of (acc*scale)
// EPI 3: p = exp(acc*scale); write Chi/Clo = split(p); atomic row sums
// ---------------------------------------------------------------------------
#define AROWB   80
#define ATILEB  (128 * AROWB)                 // 10240
#define BTILEB  (256 * AROWB)                 // 20480
#define STAGEB  (2 * ATILEB + 2 * BTILEB)     // 61440
#define GEMM_SMEM (3 * STAGEB)                // 184320

template<int EPI>
__global__ __launch_bounds__(512, 1) void gemm_bf16x3(
    const __nv_bfloat16* __restrict__ Ahi, const __nv_bfloat16* __restrict__ Alo,
    const __nv_bfloat16* __restrict__ Bhi, const __nv_bfloat16* __restrict__ Blo,
    __nv_bfloat16* __restrict__ Chi, __nv_bfloat16* __restrict__ Clo,
    float* __restrict__ rowsums,
    int M, int N, int K, long sA, long sB, long sC, long sRS, float scale)
{
    extern __shared__ char smem[];
    const uint32_t sb = smem_to_u32(smem);
    const int tid  = threadIdx.x, wid = tid >> 5, lane = tid & 31;
    const int row0 = blockIdx.y * 128;
    const int col0 = blockIdx.x * 256;
    const long zb  = blockIdx.z;
    const int wm = (wid >> 3) * 64;
    const int wn = (wid & 7) * 32;

    const char* gAh = (const char*)(Ahi + zb * sA + (long)row0 * K);
    const char* gAl = (const char*)(Alo + zb * sA + (long)row0 * K);
    const char* gBh = (const char*)(Bhi + zb * sB + (long)col0 * K);
    const char* gBl = (const char*)(Blo + zb * sB + (long)col0 * K);
    const long ld = (long)K * 2;

    const int ar_  = tid >> 2;          // 0..127
    const int acb_ = (tid & 3) * 16;
    const int NC   = K >> 5;

    auto load_stage = [&](int c) {
        const uint32_t s0 = sb + (uint32_t)((c % 3) * STAGEB);
        const long kb = (long)c * 64;
        CP_ASYNC16(s0 + (uint32_t)(ar_ * AROWB + acb_),
                   gAh + kb + (long)ar_ * ld + acb_);
        CP_ASYNC16(s0 + (uint32_t)(ATILEB + ar_ * AROWB + acb_),
                   gAl + kb + (long)ar_ * ld + acb_);
#pragma unroll
        for (int i = 0; i < 2; i++) {
            const int row = ar_ + i * 128;  // 0..255
            CP_ASYNC16(s0 + (uint32_t)(2 * ATILEB + row * AROWB + acb_),
                       gBh + kb + (long)row * ld + acb_);
            CP_ASYNC16(s0 + (uint32_t)(2 * ATILEB + BTILEB + row * AROWB + acb_),
                       gBl + kb + (long)row * ld + acb_);
        }
    };

    float acc[4][4][4];
#pragma unroll
    for (int a = 0; a < 4; a++)
#pragma unroll
        for (int b = 0; b < 4; b++)
#pragma unroll
            for (int q = 0; q < 4; q++) acc[a][b][q] = 0.f;

    load_stage(0); CP_COMMIT();
    load_stage(1); CP_COMMIT();
    load_stage(2); CP_COMMIT();

    const int aro = (wm + ((lane >> 3) & 1) * 8 + (lane & 7)) * AROWB + (lane >> 4) * 16;
    const int bro = (wn + (lane >> 4) * 8 + (lane & 7)) * AROWB + ((lane >> 3) & 1) * 16;

    for (int c = 0; c < NC; c++) {
        CP_WAIT2();
        __syncthreads();
        const uint32_t s0 = sb + (uint32_t)((c % 3) * STAGEB);

#pragma unroll
        for (int k16 = 0; k16 < 2; k16++) {
            const int kb = k16 * 32;
            uint32_t a_[4][4], bh[4][2], bl[4][2];
#pragma unroll
            for (int mt = 0; mt < 4; mt++)
                LDSM_X4(a_[mt][0], a_[mt][1], a_[mt][2], a_[mt][3],
                        s0 + (uint32_t)(aro + mt * (16 * AROWB) + kb));
#pragma unroll
            for (int p = 0; p < 2; p++) {
                LDSM_X4(bh[2*p][0], bh[2*p][1], bh[2*p+1][0], bh[2*p+1][1],
                        s0 + (uint32_t)(2 * ATILEB + bro + p * (16 * AROWB) + kb));
                LDSM_X4(bl[2*p][0], bl[2*p][1], bl[2*p+1][0], bl[2*p+1][1],
                        s0 + (uint32_t)(2 * ATILEB + BTILEB + bro + p * (16 * AROWB) + kb));
            }
#pragma unroll
            for (int mt = 0; mt < 4; mt++)
#pragma unroll
                for (int nt = 0; nt < 4; nt++)
                    mma16816(acc[mt][nt], a_[mt], bh[nt]);
#pragma unroll
            for (int mt = 0; mt < 4; mt++)
#pragma unroll
                for (int nt = 0; nt < 4; nt++)
                    mma16816(acc[mt][nt], a_[mt], bl[nt]);
#pragma unroll
            for (int mt = 0; mt < 4; mt++)
                LDSM_X4(a_[mt][0], a_[mt][1], a_[mt][2], a_[mt][3],
                        s0 + (uint32_t)(ATILEB + aro + mt * (16 * AROWB) + kb));
#pragma unroll
            for (int mt = 0; mt < 4; mt++)
#pragma unroll
                for (int nt = 0; nt < 4; nt++)
                    mma16816(acc[mt][nt], a_[mt], bh[nt]);
        }
        __syncthreads();
        if (c + 3 < NC) load_stage(c + 3);
        CP_COMMIT();
    }

    // ---- epilogue ----
    float* rowsum = (float*)smem;  // smem tiles dead now
    if (EPI == 3) {
        __syncthreads();
        if (tid < 128) rowsum[tid] = 0.f;
        __syncthreads();
    }

#pragma unroll
    for (int mt = 0; mt < 4; mt++) {
        const int rl0 = wm + mt * 16 + (lane >> 2);
        const int rg0 = row0 + rl0;
        float s0a = 0.f, s1a = 0.f;
#pragma unroll
        for (int nt = 0; nt < 4; nt++) {
            const int cg = col0 + wn + nt * 8 + (lane & 3) * 2;
            float* d = acc[mt][nt];
            float e0, e1, e2, e3;
            if (EPI == 3) {
                e0 = __expf(d[0] * scale); e1 = __expf(d[1] * scale);
                e2 = __expf(d[2] * scale); e3 = __expf(d[3] * scale);
                s0a += e0 + e1; s1a += e2 + e3;
            } else {
                e0 = d[0] * scale; e1 = d[1] * scale;
                e2 = d[2] * scale; e3 = d[3] * scale;
            }
            __nv_bfloat16 h0,h1,h2,h3,l0,l1,l2,l3;
            split1(e0,h0,l0); split1(e1,h1,l1);
            split1(e2,h2,l2); split1(e3,h3,l3);
            const long o0 = zb * sC + (long)rg0 * N + cg;
            const long o1 = o0 + 8L * N;
            *(uint32_t*)(Chi + o0) = pack2(h0, h1);
            *(uint32_t*)(Clo + o0) = pack2(l0, l1);
            *(uint32_t*)(Chi + o1) = pack2(h2, h3);
            *(uint32_t*)(Clo + o1) = pack2(l2, l3);
        }
        if (EPI == 3) {
            s0a += __shfl_xor_sync(0xffffffffu, s0a, 1);
            s0a += __shfl_xor_sync(0xffffffffu, s0a, 2);
            s1a += __shfl_xor_sync(0xffffffffu, s1a, 1);
            s1a += __shfl_xor_sync(0xffffffffu, s1a, 2);
            if ((lane & 3) == 0) {
                atomicAdd(&rowsum[rl0],     s0a);
                atomicAdd(&rowsum[rl0 + 8], s1a);
            }
        }
    }
    if (EPI == 3) {
        __syncthreads();
        if (tid < 128)
            atomicAdd(&rowsums[zb * sRS + row0 + tid], rowsum[tid]);
    }
}

// ---------------------------------------------------------------------------
// PV GEMM (NN, trans-B): Z[t,d] = (Σ_l (phi+plo)[t,l] * (hhi+hlo)[l,d]) / (s[t]+eps)
// BM=128, BN=256, BK=32, 512 threads = 16 warps (2M x 8N), 3-stage cp.async.
// ---------------------------------------------------------------------------
#define BROWB2   528                               // 512B data + 16 pad
#define BTILEB2  (32 * BROWB2)                     // 16896
#define PV_STAGE (2 * ATILEB + 2 * BTILEB2)        // 54272
#define PV_SMEM  (3 * PV_STAGE)                    // 162816

__global__ __launch_bounds__(512, 1) void gemm_pv_nn(
    const __nv_bfloat16* __restrict__ Ahi, const __nv_bfloat16* __restrict__ Alo,
    const __nv_bfloat16* __restrict__ Bhi, const __nv_bfloat16* __restrict__ Blo,
    float* __restrict__ C, const float* __restrict__ rowdiv,
    int N, int K, long sA, long sB, long sC, long sDiv)
{
    extern __shared__ char smem[];
    const uint32_t sb = smem_to_u32(smem);
    const int tid  = threadIdx.x, wid = tid >> 5, lane = tid & 31;
    const int row0 = blockIdx.y * 128;
    const int col0 = blockIdx.x * 256;
    const long zb  = blockIdx.z;
    const int wm = (wid >> 3) * 64;
    const int wn = (wid & 7) * 32;

    const char* gAh = (const char*)(Ahi + zb * sA + (long)row0 * K);
    const char* gAl = (const char*)(Alo + zb * sA + (long)row0 * K);
    const char* gBh = (const char*)(Bhi + zb * sB + col0);
    const char* gBl = (const char*)(Blo + zb * sB + col0);
    const long ldA = (long)K * 2;
    const long ldB = (long)DH_ * 2;

    const int NC = K >> 5;

    const int ar_  = tid >> 2;          // 0..127
    const int acb_ = (tid & 3) * 16;
    const int br_  = tid >> 5;          // 0..15
    const int bcb_ = (tid & 31) * 16;   // 0..496

    auto load_stage = [&](int c) {
        const uint32_t s0 = sb + (uint32_t)((c % 3) * PV_STAGE);
        const long kbA = (long)c * 64;
        const long krB = (long)c * 32;
        CP_ASYNC16(s0 + (uint32_t)(ar_ * AROWB + acb_),
                   gAh + kbA + (long)ar_ * ldA + acb_);
        CP_ASYNC16(s0 + (uint32_t)(ATILEB + ar_ * AROWB + acb_),
                   gAl + kbA + (long)ar_ * ldA + acb_);
#pragma unroll
        for (int i = 0; i < 2; i++) {
            const int krow = br_ + i * 16;
            CP_ASYNC16(s0 + (uint32_t)(2 * ATILEB + krow * BROWB2 + bcb_),
                       gBh + (krB + krow) * ldB + bcb_);
            CP_ASYNC16(s0 + (uint32_t)(2 * ATILEB + BTILEB2 + krow * BROWB2 + bcb_),
                       gBl + (krB + krow) * ldB + bcb_);
        }
    };

    float acc[4][4][4];
#pragma unroll
    for (int a = 0; a < 4; a++)
#pragma unroll
        for (int b = 0; b < 4; b++)
#pragma unroll
            for (int q = 0; q < 4; q++) acc[a][b][q] = 0.f;

    load_stage(0); CP_COMMIT();
    load_stage(1); CP_COMMIT();
    load_stage(2); CP_COMMIT();

    const int aro = (wm + ((lane >> 3) & 1) * 8 + (lane & 7)) * AROWB + (lane >> 4) * 16;
    const int btm = lane >> 3;
    const int bkr = (lane & 7) + (btm & 1) * 8;
    const int bco = (wn + (btm >> 1) * 8) * 2;

    for (int c = 0; c < NC; c++) {
        CP_WAIT2();
        __syncthreads();
        const uint32_t s0 = sb + (uint32_t)((c % 3) * PV_STAGE);

#pragma unroll
        for (int k16 = 0; k16 < 2; k16++) {
            const int kbA = k16 * 32;
            uint32_t a_[4][4], bh[4][2], bl[4][2];
#pragma unroll
            for (int mt = 0; mt < 4; mt++)
                LDSM_X4(a_[mt][0], a_[mt][1], a_[mt][2], a_[mt][3],
                        s0 + (uint32_t)(aro + mt * (16 * AROWB) + kbA));
            const uint32_t bbase = s0 + (uint32_t)(2 * ATILEB + (k16 * 16 + bkr) * BROWB2 + bco);
#pragma unroll
            for (int p = 0; p < 2; p++) {
                LDSM_X4_T(bh[2*p][0], bh[2*p][1], bh[2*p+1][0], bh[2*p+1][1],
                          bbase + (uint32_t)(p * 32));
                LDSM_X4_T(bl[2*p][0], bl[2*p][1], bl[2*p+1][0], bl[2*p+1][1],
                          bbase + (uint32_t)(BTILEB2 + p * 32));
            }
#pragma unroll
            for (int mt = 0; mt < 4; mt++)
#pragma unroll
                for (int nt = 0; nt < 4; nt++)
                    mma16816(acc[mt][nt], a_[mt], bh[nt]);
#pragma unroll
            for (int mt = 0; mt < 4; mt++)
#pragma unroll
                for (int nt = 0; nt < 4; nt++)
                    mma16816(acc[mt][nt], a_[mt], bl[nt]);
#pragma unroll
            for (int mt = 0; mt < 4; mt++)
                LDSM_X4(a_[mt][0], a_[mt][1], a_[mt][2], a_[mt][3],
                        s0 + (uint32_t)(ATILEB + aro + mt * (16 * AROWB) + kbA));
#pragma unroll
            for (int mt = 0; mt < 4; mt++)
#pragma unroll
                for (int nt = 0; nt < 4; nt++)
                    mma16816(acc[mt][nt], a_[mt], bh[nt]);
        }
        __syncthreads();
        if (c + 3 < NC) load_stage(c + 3);
        CP_COMMIT();
    }

    // ---- epilogue: divide by row sum ----
#pragma unroll
    for (int mt = 0; mt < 4; mt++) {
        const int rg0 = row0 + wm + mt * 16 + (lane >> 2);
        const int rg1 = rg0 + 8;
        const float m0 = 1.f / (rowdiv[zb * sDiv + rg0] + 1e-8f);
        const float m1 = 1.f / (rowdiv[zb * sDiv + rg1] + 1e-8f);
#pragma unroll
        for (int nt = 0; nt < 4; nt++) {
            const int cg = col0 + wn + nt * 8 + (lane & 3) * 2;
            const float* d = acc[mt][nt];
            *(float2*)(C + zb * sC + (long)rg0 * N + cg) = make_float2(d[0]*m0, d[1]*m0);
            *(float2*)(C + zb * sC + (long)rg1 * N + cg) = make_float2(d[2]*m1, d[3]*m1);
        }
    }
}

// ---------------------------------------------------------------------------
extern "C" void kernel_launch(void* const* d_in, const int* in_sizes, int n_in,
                              void* d_out, int out_size)
{
    const float* H  = (const float*)d_in[0];
    const float* G  = (const float*)d_in[1];
    const float* Wq = (const float*)d_in[2];
    const float* Wk = (const float*)d_in[3];
    float* Z = (float*)d_out;

    __nv_bfloat16 *Ghi,*Glo,*Wqhi,*Wqlo,*Wkhi,*Wklo,*Hhi,*Hlo;
    __nv_bfloat16 *Qhi,*Qlo,*Khi,*Klo,*Phi,*Plo;
    float *sump;
    cudaGetSymbolAddress((void**)&Ghi, g_Ghi);   cudaGetSymbolAddress((void**)&Glo, g_Glo);
    cudaGetSymbolAddress((void**)&Wqhi,g_Wqhi);  cudaGetSymbolAddress((void**)&Wqlo,g_Wqlo);
    cudaGetSymbolAddress((void**)&Wkhi,g_Wkhi);  cudaGetSymbolAddress((void**)&Wklo,g_Wklo);
    cudaGetSymbolAddress((void**)&Hhi, g_Hhi);   cudaGetSymbolAddress((void**)&Hlo, g_Hlo);
    cudaGetSymbolAddress((void**)&Qhi, g_Qhi);   cudaGetSymbolAddress((void**)&Qlo, g_Qlo);
    cudaGetSymbolAddress((void**)&Khi, g_Khi);   cudaGetSymbolAddress((void**)&Klo, g_Klo);
    cudaGetSymbolAddress((void**)&Phi, g_Phi);   cudaGetSymbolAddress((void**)&Plo, g_Plo);
    cudaGetSymbolAddress((void**)&sump,g_sum);

    cudaFuncSetAttribute(gemm_bf16x3<1>, cudaFuncAttributeMaxDynamicSharedMemorySize, GEMM_SMEM);
    cudaFuncSetAttribute(gemm_bf16x3<3>, cudaFuncAttributeMaxDynamicSharedMemorySize, GEMM_SMEM);
    cudaFuncSetAttribute(gemm_pv_nn,     cudaFuncAttributeMaxDynamicSharedMemorySize, PV_SMEM);

    // 1) bf16 hi/lo splits + zero row sums
    { int n4 = B_*T_*DG_/4;  split_f32<<<(n4+255)/256, 256>>>(G,  Ghi,  Glo,  n4); }
    { int n4 = P_*DG_/4;     split_f32<<<(n4+255)/256, 256>>>(Wq, Wqhi, Wqlo, n4); }
    { int n4 = P_*DH_/4;     split_f32<<<(n4+255)/256, 256>>>(Wk, Wkhi, Wklo, n4); }
    { int n4 = B_*L_*DH_/4;  split_f32<<<(n4+255)/256, 256>>>(H,  Hhi,  Hlo,  n4); }
    zero_f32<<<(B_*T_+255)/256, 256>>>(sump, B_*T_);

    // 2) Q = G * Wq^T -> Q hi/lo [8192,256]
    gemm_bf16x3<1><<<dim3(P_/256, (B_*T_)/128, 1), 512, GEMM_SMEM>>>(
        Ghi, Glo, Wqhi, Wqlo, Qhi, Qlo, nullptr,
        B_*T_, P_, DG_, 0, 0, 0, 0, 1.f);

    // 3) K = H * Wk^T -> K hi/lo [32768,256]
    gemm_bf16x3<1><<<dim3(P_/256, (B_*L_)/128, 1), 512, GEMM_SMEM>>>(
        Hhi, Hlo, Wkhi, Wklo, Khi, Klo, nullptr,
        B_*L_, P_, DH_, 0, 0, 0, 0, 1.f);

    // 4) P = exp((1/16) Q K^T) hi/lo + row sums (no max needed: |logit| <~ 2)
    gemm_bf16x3<3><<<dim3(L_/256, T_/128, B_), 512, GEMM_SMEM>>>(
        Qhi, Qlo, Khi, Klo, Phi, Plo, sump,
        T_, L_, P_, (long)T_*P_, (long)L_*P_, (long)T_*L_, T_, 0.0625f);

    // 5) Z = (P * H) / (s+eps)   (NN, trans-B reads H directly)
    gemm_pv_nn<<<dim3(DH_/256, T_/128, B_), 512, PV_SMEM>>>(
        Phi, Plo, Hhi, Hlo, Z, sump,
        DH_, L_, (long)T_*L_, (long)L_*DH_, (long)T_*DH_, T_);
}

// round 10
// speedup vs baseline: 1.0649x; 1.0649x over previous
#include <cuda_runtime.h>
#include <cuda_bf16.h>
#include <cstdint>

// Problem: H[8,4096,1024] G[8,1024,768] Wq[256,768] Wk[256,1024] -> Z[8,1024,1024]
#define B_  8
#define L_  4096
#define DH_ 1024
#define T_  1024
#define DG_ 768
#define P_  256

// ---------------------------------------------------------------------------
// PTX helpers — base-target (sm_80+) features only: mma.sync, ldmatrix, cp.async
// ---------------------------------------------------------------------------
__device__ __forceinline__ uint32_t smem_to_u32(const void* p) {
    uint32_t a;
    asm("{ .reg .u64 t; cvta.to.shared.u64 t, %1; cvt.u32.u64 %0, t; }" : "=r"(a) : "l"(p));
    return a;
}
#define CP_ASYNC16(sa, g) \
    asm volatile("cp.async.cg.shared.global [%0], [%1], 16;" :: "r"(sa), "l"(g))
#define CP_COMMIT() asm volatile("cp.async.commit_group;")
#define CP_WAIT1()  asm volatile("cp.async.wait_group 1;")

#define LDSM_X4(r0, r1, r2, r3, addr) \
    asm volatile("ldmatrix.sync.aligned.m8n8.x4.shared.b16 {%0,%1,%2,%3}, [%4];" \
                 : "=r"(r0), "=r"(r1), "=r"(r2), "=r"(r3) : "r"(addr))
#define LDSM_X4_T(r0, r1, r2, r3, addr) \
    asm volatile("ldmatrix.sync.aligned.m8n8.x4.trans.shared.b16 {%0,%1,%2,%3}, [%4];" \
                 : "=r"(r0), "=r"(r1), "=r"(r2), "=r"(r3) : "r"(addr))

__device__ __forceinline__ void mma16816(float* d, const uint32_t* a, const uint32_t* b) {
    asm volatile(
        "mma.sync.aligned.m16n8k16.row.col.f32.bf16.bf16.f32 "
        "{%0,%1,%2,%3}, {%4,%5,%6,%7}, {%8,%9}, {%0,%1,%2,%3};"
        : "+f"(d[0]), "+f"(d[1]), "+f"(d[2]), "+f"(d[3])
        : "r"(a[0]), "r"(a[1]), "r"(a[2]), "r"(a[3]), "r"(b[0]), "r"(b[1]));
}

__device__ __forceinline__ void split1(float f, __nv_bfloat16& h, __nv_bfloat16& l) {
    h = __float2bfloat16(f);
    l = __float2bfloat16(f - __bfloat162float(h));
}
__device__ __forceinline__ uint32_t pack2(__nv_bfloat16 a, __nv_bfloat16 b) {
    return ((uint32_t)*(uint16_t*)&b << 16) | *(uint16_t*)&a;
}

// ---------------------------------------------------------------------------
// Scratch (device globals; allocation-free)
// ---------------------------------------------------------------------------
__device__ __align__(16) __nv_bfloat16 g_Ghi[(size_t)B_*T_*DG_],  g_Glo[(size_t)B_*T_*DG_];
__device__ __align__(16) __nv_bfloat16 g_Wqhi[(size_t)P_*DG_],    g_Wqlo[(size_t)P_*DG_];
__device__ __align__(16) __nv_bfloat16 g_Wkhi[(size_t)P_*DH_],    g_Wklo[(size_t)P_*DH_];
__device__ __align__(16) __nv_bfloat16 g_Hhi[(size_t)B_*L_*DH_],  g_Hlo[(size_t)B_*L_*DH_];
__device__ __align__(16) __nv_bfloat16 g_Qhi[(size_t)B_*T_*P_],   g_Qlo[(size_t)B_*T_*P_];
__device__ __align__(16) __nv_bfloat16 g_Khi[(size_t)B_*L_*P_],   g_Klo[(size_t)B_*L_*P_];
__device__ __align__(16) __nv_bfloat16 g_Phi[(size_t)B_*T_*L_],   g_Plo[(size_t)B_*T_*L_];
__device__ float g_sum[(size_t)B_*T_];

// ---------------------------------------------------------------------------
// Elementwise fp32 -> bf16 hi/lo split
// ---------------------------------------------------------------------------
__global__ __launch_bounds__(256) void split_f32(
    const float* __restrict__ x, __nv_bfloat16* __restrict__ hi,
    __nv_bfloat16* __restrict__ lo, int n4)
{
    int i = blockIdx.x * 256 + threadIdx.x;
    if (i >= n4) return;
    float4 v = ((const float4*)x)[i];
    __nv_bfloat16 h0,h1,h2,h3,l0,l1,l2,l3;
    split1(v.x,h0,l0); split1(v.y,h1,l1); split1(v.z,h2,l2); split1(v.w,h3,l3);
    ((uint2*)hi)[i] = make_uint2(pack2(h0,h1), pack2(h2,h3));
    ((uint2*)lo)[i] = make_uint2(pack2(l0,l1), pack2(l2,l3));
}

__global__ __launch_bounds__(256) void zero_f32(float* __restrict__ p, int n) {
    int i = blockIdx.x * 256 + threadIdx.x;
    if (i < n) p[i] = 0.f;
}

// ---------------------------------------------------------------------------
// HMMA bf16 3-split NT GEMM:  C[M,N] = (Ahi+Alo)[M,K] * (Bhi+Blo)[N,K]^T
// BM=BN=128, BK=32, 256 threads = 8 warps (2M x 4N), 2-stage cp.async,
// 2 CTAs/SM (smem 80KB/CTA, regs capped by launch_bounds(256,2)).
// Register-lean inner loop: (ah,bh),(ah,bl) then ah<-al,(al,bh).
// EPI 1: write Chi/Clo bf16 split of (acc*scale)
// EPI 3: p = exp(acc*scale); write Chi/Clo = split(p); atomic row sums
// ---------------------------------------------------------------------------
#define AROWB  80
#define TILEB  (128 * AROWB)        // 10240 B per operand tile
#define STAGEB (4 * TILEB)          // Ah, Al, Bh, Bl = 40960
#define GEMM_SMEM (2 * STAGEB)      // 81920 B

template<int EPI>
__global__ __launch_bounds__(256, 2) void gemm_bf16x3(
    const __nv_bfloat16* __restrict__ Ahi, const __nv_bfloat16* __restrict__ Alo,
    const __nv_bfloat16* __restrict__ Bhi, const __nv_bfloat16* __restrict__ Blo,
    __nv_bfloat16* __restrict__ Chi, __nv_bfloat16* __restrict__ Clo,
    float* __restrict__ rowsums,
    int M, int N, int K, long sA, long sB, long sC, long sRS, float scale)
{
    extern __shared__ char smem[];
    const uint32_t sb = smem_to_u32(smem);
    const int tid  = threadIdx.x, wid = tid >> 5, lane = tid & 31;
    const int row0 = blockIdx.y * 128;
    const int col0 = blockIdx.x * 128;
    const long zb  = blockIdx.z;
    const int wm = (wid >> 2) * 64;
    const int wn = (wid & 3) * 32;

    const char* gT[4] = {
        (const char*)(Ahi + zb * sA + (long)row0 * K),
        (const char*)(Alo + zb * sA + (long)row0 * K),
        (const char*)(Bhi + zb * sB + (long)col0 * K),
        (const char*)(Blo + zb * sB + (long)col0 * K) };
    const long ld = (long)K * 2;

    const int r_  = tid >> 2;
    const int cb_ = (tid & 3) * 16;
    const int NC  = K >> 5;

    auto load_stage = [&](int c) {
        const uint32_t s0 = sb + (uint32_t)((c & 1) * STAGEB);
        const long kb = (long)c * 64;
#pragma unroll
        for (int t = 0; t < 4; t++) {
            const char* g = gT[t] + kb;
#pragma unroll
            for (int i = 0; i < 2; i++) {
                const int row = r_ + i * 64;
                CP_ASYNC16(s0 + (uint32_t)(t * TILEB + row * AROWB + cb_),
                           g + (long)row * ld + cb_);
            }
        }
    };

    float acc[4][4][4];
#pragma unroll
    for (int a = 0; a < 4; a++)
#pragma unroll
        for (int b = 0; b < 4; b++)
#pragma unroll
            for (int q = 0; q < 4; q++) acc[a][b][q] = 0.f;

    load_stage(0); CP_COMMIT();
    load_stage(1); CP_COMMIT();

    const int aro = (wm + ((lane >> 3) & 1) * 8 + (lane & 7)) * AROWB + (lane >> 4) * 16;
    const int bro = (wn + (lane >> 4) * 8 + (lane & 7)) * AROWB + ((lane >> 3) & 1) * 16;

    for (int c = 0; c < NC; c++) {
        CP_WAIT1();
        __syncthreads();
        const uint32_t s0 = sb + (uint32_t)((c & 1) * STAGEB);

#pragma unroll
        for (int k16 = 0; k16 < 2; k16++) {
            const int kb = k16 * 32;
            uint32_t a_[4][4], bh[4][2], bl[4][2];
#pragma unroll
            for (int mt = 0; mt < 4; mt++)
                LDSM_X4(a_[mt][0], a_[mt][1], a_[mt][2], a_[mt][3],
                        s0 + (uint32_t)(aro + mt * (16 * AROWB) + kb));
#pragma unroll
            for (int p = 0; p < 2; p++) {
                LDSM_X4(bh[2*p][0], bh[2*p][1], bh[2*p+1][0], bh[2*p+1][1],
                        s0 + (uint32_t)(2 * TILEB + bro + p * (16 * AROWB) + kb));
                LDSM_X4(bl[2*p][0], bl[2*p][1], bl[2*p+1][0], bl[2*p+1][1],
                        s0 + (uint32_t)(3 * TILEB + bro + p * (16 * AROWB) + kb));
            }
#pragma unroll
            for (int mt = 0; mt < 4; mt++)
#pragma unroll
                for (int nt = 0; nt < 4; nt++)
                    mma16816(acc[mt][nt], a_[mt], bh[nt]);
#pragma unroll
            for (int mt = 0; mt < 4; mt++)
#pragma unroll
                for (int nt = 0; nt < 4; nt++)
                    mma16816(acc[mt][nt], a_[mt], bl[nt]);
#pragma unroll
            for (int mt = 0; mt < 4; mt++)
                LDSM_X4(a_[mt][0], a_[mt][1], a_[mt][2], a_[mt][3],
                        s0 + (uint32_t)(TILEB + aro + mt * (16 * AROWB) + kb));
#pragma unroll
            for (int mt = 0; mt < 4; mt++)
#pragma unroll
                for (int nt = 0; nt < 4; nt++)
                    mma16816(acc[mt][nt], a_[mt], bh[nt]);
        }
        __syncthreads();
        if (c + 2 < NC) load_stage(c + 2);
        CP_COMMIT();
    }

    // ---- epilogue ----
    float* rowsum = (float*)smem;  // smem tiles dead now
    if (EPI == 3) {
        __syncthreads();
        if (tid < 128) rowsum[tid] = 0.f;
        __syncthreads();
    }

#pragma unroll
    for (int mt = 0; mt < 4; mt++) {
        const int rl0 = wm + mt * 16 + (lane >> 2);
        const int rg0 = row0 + rl0;
        float s0a = 0.f, s1a = 0.f;
#pragma unroll
        for (int nt = 0; nt < 4; nt++) {
            const int cg = col0 + wn + nt * 8 + (lane & 3) * 2;
            float* d = acc[mt][nt];
            float e0, e1, e2, e3;
            if (EPI == 3) {
                e0 = __expf(d[0] * scale); e1 = __expf(d[1] * scale);
                e2 = __expf(d[2] * scale); e3 = __expf(d[3] * scale);
                s0a += e0 + e1; s1a += e2 + e3;
            } else {
                e0 = d[0] * scale; e1 = d[1] * scale;
                e2 = d[2] * scale; e3 = d[3] * scale;
            }
            __nv_bfloat16 h0,h1,h2,h3,l0,l1,l2,l3;
            split1(e0,h0,l0); split1(e1,h1,l1);
            split1(e2,h2,l2); split1(e3,h3,l3);
            const long o0 = zb * sC + (long)rg0 * N + cg;
            const long o1 = o0 + 8L * N;
            *(uint32_t*)(Chi + o0) = pack2(h0, h1);
            *(uint32_t*)(Clo + o0) = pack2(l0, l1);
            *(uint32_t*)(Chi + o1) = pack2(h2, h3);
            *(uint32_t*)(Clo + o1) = pack2(l2, l3);
        }
        if (EPI == 3) {
            s0a += __shfl_xor_sync(0xffffffffu, s0a, 1);
            s0a += __shfl_xor_sync(0xffffffffu, s0a, 2);
            s1a += __shfl_xor_sync(0xffffffffu, s1a, 1);
            s1a += __shfl_xor_sync(0xffffffffu, s1a, 2);
            if ((lane & 3) == 0) {
                atomicAdd(&rowsum[rl0],     s0a);
                atomicAdd(&rowsum[rl0 + 8], s1a);
            }
        }
    }
    if (EPI == 3) {
        __syncthreads();
        if (tid < 128)
            atomicAdd(&rowsums[zb * sRS + row0 + tid], rowsum[tid]);
    }
}

// ---------------------------------------------------------------------------
// PV GEMM (NN, trans-B): Z[t,d] = (Σ_l (phi+plo)[t,l] * (hhi+hlo)[l,d]) / (s[t]+eps)
// BM=BN=128, BK=32, 8 warps, 2-stage cp.async, 2 CTAs/SM.
// ---------------------------------------------------------------------------
#define BROWB   272
#define BTILEB  (32 * BROWB)                 // 8704 B per B operand tile
#define PV_STAGE (2 * TILEB + 2 * BTILEB)    // 37888
#define PV_SMEM  (2 * PV_STAGE)              // 75776

__global__ __launch_bounds__(256, 2) void gemm_pv_nn(
    const __nv_bfloat16* __restrict__ Ahi, const __nv_bfloat16* __restrict__ Alo,
    const __nv_bfloat16* __restrict__ Bhi, const __nv_bfloat16* __restrict__ Blo,
    float* __restrict__ C, const float* __restrict__ rowdiv,
    int N, int K, long sA, long sB, long sC, long sDiv)
{
    extern __shared__ char smem[];
    const uint32_t sb = smem_to_u32(smem);
    const int tid  = threadIdx.x, wid = tid >> 5, lane = tid & 31;
    const int row0 = blockIdx.y * 128;
    const int col0 = blockIdx.x * 128;
    const long zb  = blockIdx.z;
    const int wm = (wid >> 2) * 64;
    const int wn = (wid & 3) * 32;

    const char* gAh = (const char*)(Ahi + zb * sA + (long)row0 * K);
    const char* gAl = (const char*)(Alo + zb * sA + (long)row0 * K);
    const char* gBh = (const char*)(Bhi + zb * sB + col0);
    const char* gBl = (const char*)(Blo + zb * sB + col0);
    const long ldA = (long)K * 2;
    const long ldB = (long)DH_ * 2;

    const int NC = K >> 5;

    const int ar_  = tid >> 2;
    const int acb_ = (tid & 3) * 16;
    const int br_  = tid >> 4;         // 0..15
    const int bcb_ = (tid & 15) * 16;  // 0..240

    auto load_stage = [&](int c) {
        const uint32_t s0 = sb + (uint32_t)((c & 1) * PV_STAGE);
        const long kbA = (long)c * 64;
        const long krB = (long)c * 32;
#pragma unroll
        for (int i = 0; i < 2; i++) {
            const int row = ar_ + i * 64;
            CP_ASYNC16(s0 + (uint32_t)(row * AROWB + acb_),
                       gAh + kbA + (long)row * ldA + acb_);
            CP_ASYNC16(s0 + (uint32_t)(TILEB + row * AROWB + acb_),
                       gAl + kbA + (long)row * ldA + acb_);
        }
#pragma unroll
        for (int i = 0; i < 2; i++) {
            const int krow = br_ + i * 16;
            CP_ASYNC16(s0 + (uint32_t)(2 * TILEB + krow * BROWB + bcb_),
                       gBh + (krB + krow) * ldB + bcb_);
            CP_ASYNC16(s0 + (uint32_t)(2 * TILEB + BTILEB + krow * BROWB + bcb_),
                       gBl + (krB + krow) * ldB + bcb_);
        }
    };

    float acc[4][4][4];
#pragma unroll
    for (int a = 0; a < 4; a++)
#pragma unroll
        for (int b = 0; b < 4; b++)
#pragma unroll
            for (int q = 0; q < 4; q++) acc[a][b][q] = 0.f;

    load_stage(0); CP_COMMIT();
    load_stage(1); CP_COMMIT();

    const int aro = (wm + ((lane >> 3) & 1) * 8 + (lane & 7)) * AROWB + (lane >> 4) * 16;
    const int btm = lane >> 3;
    const int bkr = (lane & 7) + (btm & 1) * 8;
    const int bco = (wn + (btm >> 1) * 8) * 2;

    for (int c = 0; c < NC; c++) {
        CP_WAIT1();
        __syncthreads();
        const uint32_t s0 = sb + (uint32_t)((c & 1) * PV_STAGE);

#pragma unroll
        for (int k16 = 0; k16 < 2; k16++) {
            const int kbA = k16 * 32;
            uint32_t a_[4][4], bh[4][2], bl[4][2];
#pragma unroll
            for (int mt = 0; mt < 4; mt++)
                LDSM_X4(a_[mt][0], a_[mt][1], a_[mt][2], a_[mt][3],
                        s0 + (uint32_t)(aro + mt * (16 * AROWB) + kbA));
            const uint32_t bbase = s0 + (uint32_t)(2 * TILEB + (k16 * 16 + bkr) * BROWB + bco);
#pragma unroll
            for (int p = 0; p < 2; p++) {
                LDSM_X4_T(bh[2*p][0], bh[2*p][1], bh[2*p+1][0], bh[2*p+1][1],
                          bbase + (uint32_t)(p * 32));
                LDSM_X4_T(bl[2*p][0], bl[2*p][1], bl[2*p+1][0], bl[2*p+1][1],
                          bbase + (uint32_t)(BTILEB + p * 32));
            }
#pragma unroll
            for (int mt = 0; mt < 4; mt++)
#pragma unroll
                for (int nt = 0; nt < 4; nt++)
                    mma16816(acc[mt][nt], a_[mt], bh[nt]);
#pragma unroll
            for (int mt = 0; mt < 4; mt++)
#pragma unroll
                for (int nt = 0; nt < 4; nt++)
                    mma16816(acc[mt][nt], a_[mt], bl[nt]);
#pragma unroll
            for (int mt = 0; mt < 4; mt++)
                LDSM_X4(a_[mt][0], a_[mt][1], a_[mt][2], a_[mt][3],
                        s0 + (uint32_t)(TILEB + aro + mt * (16 * AROWB) + kbA));
#pragma unroll
            for (int mt = 0; mt < 4; mt++)
#pragma unroll
                for (int nt = 0; nt < 4; nt++)
                    mma16816(acc[mt][nt], a_[mt], bh[nt]);
        }
        __syncthreads();
        if (c + 2 < NC) load_stage(c + 2);
        CP_COMMIT();
    }

    // ---- epilogue: divide by row sum ----
#pragma unroll
    for (int mt = 0; mt < 4; mt++) {
        const int rg0 = row0 + wm + mt * 16 + (lane >> 2);
        const int rg1 = rg0 + 8;
        const float m0 = 1.f / (rowdiv[zb * sDiv + rg0] + 1e-8f);
        const float m1 = 1.f / (rowdiv[zb * sDiv + rg1] + 1e-8f);
#pragma unroll
        for (int nt = 0; nt < 4; nt++) {
            const int cg = col0 + wn + nt * 8 + (lane & 3) * 2;
            const float* d = acc[mt][nt];
            *(float2*)(C + zb * sC + (long)rg0 * N + cg) = make_float2(d[0]*m0, d[1]*m0);
            *(float2*)(C + zb * sC + (long)rg1 * N + cg) = make_float2(d[2]*m1, d[3]*m1);
        }
    }
}

// ---------------------------------------------------------------------------
extern "C" void kernel_launch(void* const* d_in, const int* in_sizes, int n_in,
                              void* d_out, int out_size)
{
    const float* H  = (const float*)d_in[0];
    const float* G  = (const float*)d_in[1];
    const float* Wq = (const float*)d_in[2];
    const float* Wk = (const float*)d_in[3];
    float* Z = (float*)d_out;

    __nv_bfloat16 *Ghi,*Glo,*Wqhi,*Wqlo,*Wkhi,*Wklo,*Hhi,*Hlo;
    __nv_bfloat16 *Qhi,*Qlo,*Khi,*Klo,*Phi,*Plo;
    float *sump;
    cudaGetSymbolAddress((void**)&Ghi, g_Ghi);   cudaGetSymbolAddress((void**)&Glo, g_Glo);
    cudaGetSymbolAddress((void**)&Wqhi,g_Wqhi);  cudaGetSymbolAddress((void**)&Wqlo,g_Wqlo);
    cudaGetSymbolAddress((void**)&Wkhi,g_Wkhi);  cudaGetSymbolAddress((void**)&Wklo,g_Wklo);
    cudaGetSymbolAddress((void**)&Hhi, g_Hhi);   cudaGetSymbolAddress((void**)&Hlo, g_Hlo);
    cudaGetSymbolAddress((void**)&Qhi, g_Qhi);   cudaGetSymbolAddress((void**)&Qlo, g_Qlo);
    cudaGetSymbolAddress((void**)&Khi, g_Khi);   cudaGetSymbolAddress((void**)&Klo, g_Klo);
    cudaGetSymbolAddress((void**)&Phi, g_Phi);   cudaGetSymbolAddress((void**)&Plo, g_Plo);
    cudaGetSymbolAddress((void**)&sump,g_sum);

    cudaFuncSetAttribute(gemm_bf16x3<1>, cudaFuncAttributeMaxDynamicSharedMemorySize, GEMM_SMEM);
    cudaFuncSetAttribute(gemm_bf16x3<3>, cudaFuncAttributeMaxDynamicSharedMemorySize, GEMM_SMEM);
    cudaFuncSetAttribute(gemm_pv_nn,     cudaFuncAttributeMaxDynamicSharedMemorySize, PV_SMEM);

    // 1) bf16 hi/lo splits + zero row sums
    { int n4 = B_*T_*DG_/4;  split_f32<<<(n4+255)/256, 256>>>(G,  Ghi,  Glo,  n4); }
    { int n4 = P_*DG_/4;     split_f32<<<(n4+255)/256, 256>>>(Wq, Wqhi, Wqlo, n4); }
    { int n4 = P_*DH_/4;     split_f32<<<(n4+255)/256, 256>>>(Wk, Wkhi, Wklo, n4); }
    { int n4 = B_*L_*DH_/4;  split_f32<<<(n4+255)/256, 256>>>(H,  Hhi,  Hlo,  n4); }
    zero_f32<<<(B_*T_+255)/256, 256>>>(sump, B_*T_);

    // 2) Q = G * Wq^T -> Q hi/lo [8192,256]
    gemm_bf16x3<1><<<dim3(P_/128, (B_*T_)/128, 1), 256, GEMM_SMEM>>>(
        Ghi, Glo, Wqhi, Wqlo, Qhi, Qlo, nullptr,
        B_*T_, P_, DG_, 0, 0, 0, 0, 1.f);

    // 3) K = H * Wk^T -> K hi/lo [32768,256]
    gemm_bf16x3<1><<<dim3(P_/128, (B_*L_)/128, 1), 256, GEMM_SMEM>>>(
        Hhi, Hlo, Wkhi, Wklo, Khi, Klo, nullptr,
        B_*L_, P_, DH_, 0, 0, 0, 0, 1.f);

    // 4) P = exp((1/16) Q K^T) hi/lo + row sums (no max needed: |logit| <~ 2)
    gemm_bf16x3<3><<<dim3(L_/128, T_/128, B_), 256, GEMM_SMEM>>>(
        Qhi, Qlo, Khi, Klo, Phi, Plo, sump,
        T_, L_, P_, (long)T_*P_, (long)L_*P_, (long)T_*L_, T_, 0.0625f);

    // 5) Z = (P * H) / (s+eps)   (NN, trans-B reads H directly)
    gemm_pv_nn<<<dim3(DH_/128, T_/128, B_), 256, PV_SMEM>>>(
        Phi, Plo, Hhi, Hlo, Z, sump,
        DH_, L_, (long)T_*L_, (long)L_*DH_, (long)T_*DH_, T_);
}